// round 4
// baseline (speedup 1.0000x reference)
#include <cuda_runtime.h>
#include <math.h>

#define EDIM   256
#define HDIM   512
#define BATCH  32
#define SEQ    512
#define G3     1536
#define NCTA   128
#define DPC    4
#define GRUT   512

// ---- scratch (device globals; no allocations allowed) ----
__device__ float d_induced[EDIM];
__device__ float d_e2[SEQ * BATCH * EDIM];            // [t][b][k]
__device__ float d_xi[(size_t)SEQ * G3 * BATCH];      // [t][g][b]
__device__ float d_h[2 * BATCH * HDIM];               // [buf][b][k]
__device__ float d_pooled[BATCH * HDIM];              // [b][d]
__device__ unsigned d_cnt;
__device__ unsigned d_gen;

// ---- init: induced = induction @ unk, h0 = 0, barrier reset ----
__global__ void init_kernel(const float* __restrict__ induction,
                            const float* __restrict__ unk) {
    int i = threadIdx.x;                               // 256 threads
    if (i == 0) { d_cnt = 0u; d_gen = 0u; }
    const float* row = induction + (size_t)i * EDIM;
    float s = 0.f;
    #pragma unroll 4
    for (int j = 0; j < EDIM; j++) s += row[j] * unk[j];
    d_induced[i] = s;
    for (int f = i; f < BATCH * HDIM; f += 256) d_h[f] = 0.f;
}

// ---- gather: e2[t][b][:] = emb_table[tok] or induced ----
__global__ void gather_kernel(const int* __restrict__ x,
                              const float* __restrict__ emb) {
    int gid = blockIdx.x * 256 + threadIdx.x;          // one float4 each
    int row = gid >> 6;                                // (t,b)
    int q   = gid & 63;
    int t = row >> 5, b = row & 31;
    int tok = x[b * SEQ + t];
    float4 v;
    if (tok < 0) v = ((const float4*)d_induced)[q];
    else         v = *((const float4*)(emb + (size_t)tok * EDIM) + q);
    ((float4*)d_e2)[gid] = v;
}

// ---- xi GEMM: xi[t][g][b] = sum_k e2[t][b][k]*W_ih[g][k] + b_ih[g] ----
// grid (SEQ, 12); CTA = one t x 128 gates. warp = 16 gates, lane = batch.
__global__ void __launch_bounds__(256) xi_gemm_kernel(const float* __restrict__ W_ih,
                                                      const float* __restrict__ b_ih) {
    __shared__ __align__(16) float e_s[32 * 260];      // padded
    __shared__ __align__(16) float w_s[128 * 16];
    int t  = blockIdx.x;
    int g0 = blockIdx.y * 128;
    int tid = threadIdx.x;
    int w = tid >> 5, lane = tid & 31;

    const float* esrc = d_e2 + (size_t)t * BATCH * EDIM;
    for (int f = tid; f < 32 * 256; f += 256)
        e_s[(f >> 8) * 260 + (f & 255)] = esrc[f];

    float acc[16];
    #pragma unroll
    for (int g = 0; g < 16; g++) acc[g] = 0.f;

    for (int kc = 0; kc < 256; kc += 16) {
        __syncthreads();
        for (int f = tid; f < 2048; f += 256)
            w_s[f] = W_ih[(size_t)(g0 + (f >> 4)) * EDIM + kc + (f & 15)];
        __syncthreads();
        const float* hrow = e_s + lane * 260 + kc;
        #pragma unroll
        for (int k4 = 0; k4 < 16; k4 += 4) {
            float4 hv = *(const float4*)(hrow + k4);
            #pragma unroll
            for (int g = 0; g < 16; g++) {
                float4 wv = *(const float4*)(w_s + (w * 16 + g) * 16 + k4);
                acc[g] += hv.x * wv.x + hv.y * wv.y + hv.z * wv.z + hv.w * wv.w;
            }
        }
    }
    float* orow = d_xi + ((size_t)t * G3 + g0 + w * 16) * BATCH + lane;
    #pragma unroll
    for (int g = 0; g < 16; g++)
        orow[(size_t)g * BATCH] = acc[g] + b_ih[g0 + w * 16 + g];
}

// ---- GRU recurrence: persistent, weight-stationary, grid barrier ----
// CTA owns dims d0..d0+3. warp w: dl = w>>2 (local dim), kc = w&3 (128-K chunk).
__global__ void __launch_bounds__(GRUT, 1)
gru_kernel(const float* __restrict__ W_hh, const float* __restrict__ b_hh) {
    extern __shared__ float sm[];
    float* h_s = sm;                        // [32][516]
    float* w_s = sm + 32 * 516;             // [12][512]
    float* red = w_s + 12 * 512;            // [16][3][32]

    const int tid  = threadIdx.x;
    const int w    = tid >> 5, lane = tid & 31;
    const int dl   = w >> 2,   kc   = w & 3;
    const int d    = blockIdx.x * DPC + dl;

    for (int f = tid; f < 12 * 512; f += GRUT) {
        int r = f >> 9, k = f & 511;
        int gate = r >> 2, dd = r & 3;
        w_s[f] = W_hh[((size_t)gate * HDIM + blockIdx.x * DPC + dd) * HDIM + k];
    }
    float bh0 = 0.f, bh1 = 0.f, bh2 = 0.f;
    if (kc == 0) { bh0 = b_hh[d]; bh1 = b_hh[HDIM + d]; bh2 = b_hh[2 * HDIM + d]; }
    float maxacc = -INFINITY;
    __syncthreads();

    for (int t = 0; t < SEQ; t++) {
        // 1) broadcast h_prev -> smem (coalesced float4)
        const float4* hsrc = (const float4*)(d_h + (t & 1) * BATCH * HDIM);
        #pragma unroll
        for (int i = 0, f = tid; i < 8; i++, f += GRUT) {
            int b = f >> 7, k4 = f & 127;
            float4 v = hsrc[f];
            *(float4*)(h_s + b * 516 + k4 * 4) = v;
        }
        __syncthreads();

        // 2) partial dot products: 3 gate rows x 128-K chunk, lane = batch
        float4 a0 = {0,0,0,0}, a1 = {0,0,0,0}, a2 = {0,0,0,0};
        const float* hrow = h_s + lane * 516 + kc * 128;
        const float* w0 = w_s + (0 * 4 + dl) * 512 + kc * 128;
        const float* w1 = w_s + (1 * 4 + dl) * 512 + kc * 128;
        const float* w2 = w_s + (2 * 4 + dl) * 512 + kc * 128;
        #pragma unroll 4
        for (int i = 0; i < 128; i += 4) {
            float4 hv = *(const float4*)(hrow + i);
            float4 v0 = *(const float4*)(w0 + i);
            float4 v1 = *(const float4*)(w1 + i);
            float4 v2 = *(const float4*)(w2 + i);
            a0.x += hv.x * v0.x; a0.y += hv.y * v0.y; a0.z += hv.z * v0.z; a0.w += hv.w * v0.w;
            a1.x += hv.x * v1.x; a1.y += hv.y * v1.y; a1.z += hv.z * v1.z; a1.w += hv.w * v1.w;
            a2.x += hv.x * v2.x; a2.y += hv.y * v2.y; a2.z += hv.z * v2.z; a2.w += hv.w * v2.w;
        }
        red[(w * 3 + 0) * 32 + lane] = a0.x + a0.y + a0.z + a0.w;
        red[(w * 3 + 1) * 32 + lane] = a1.x + a1.y + a1.z + a1.w;
        red[(w * 3 + 2) * 32 + lane] = a2.x + a2.y + a2.z + a2.w;
        __syncthreads();

        // 3) finalize gates (warps with kc==0; one warp per local dim, lane = batch)
        if (kc == 0) {
            int base = dl * 4 * 3 * 32;
            float sr = red[base + 0*32 + lane] + red[base + 3*32 + lane]
                     + red[base + 6*32 + lane] + red[base + 9*32 + lane];
            float sz = red[base + 1*32 + lane] + red[base + 4*32 + lane]
                     + red[base + 7*32 + lane] + red[base + 10*32 + lane];
            float sn = red[base + 2*32 + lane] + red[base + 5*32 + lane]
                     + red[base + 8*32 + lane] + red[base + 11*32 + lane];
            const float* xib = d_xi + (size_t)t * G3 * BATCH;
            float xr = xib[(size_t)(0 * HDIM + d) * BATCH + lane];
            float xz = xib[(size_t)(1 * HDIM + d) * BATCH + lane];
            float xn = xib[(size_t)(2 * HDIM + d) * BATCH + lane];
            float rg = 1.f / (1.f + expf(-(xr + sr + bh0)));
            float zg = 1.f / (1.f + expf(-(xz + sz + bh1)));
            float ng = tanhf(xn + rg * (sn + bh2));      // torch GRU: b_hh_n inside r*(.)
            float hp = h_s[lane * 516 + d];
            float hnew = (1.f - zg) * ng + zg * hp;
            maxacc = fmaxf(maxacc, hnew);
            d_h[((t + 1) & 1) * BATCH * HDIM + lane * HDIM + d] = hnew;
        }

        // 4) grid barrier (monotonic counter within this launch)
        __syncthreads();
        __threadfence();
        if (tid == 0) {
            unsigned target = (unsigned)(t + 1) * NCTA;
            unsigned a = atomicAdd(&d_cnt, 1u) + 1u;
            if (a == target) {
                atomicExch(&d_gen, (unsigned)(t + 1));
            } else {
                while (*((volatile unsigned*)&d_gen) < (unsigned)(t + 1)) { }
            }
            __threadfence();
        }
        __syncthreads();
    }
    if (kc == 0) d_pooled[lane * HDIM + d] = maxacc;
}

// ---- projection: out[b][c] = pooled[b] . W_proj[c] + b_proj[c] ----
__global__ void proj_kernel(const float* __restrict__ Wp,
                            const float* __restrict__ bp,
                            float* __restrict__ out) {
    __shared__ float red[128];
    int b = blockIdx.x >> 1, c = blockIdx.x & 1;
    int tid = threadIdx.x;                              // 128 threads
    const float* pr = d_pooled + b * HDIM;
    const float* wr = Wp + c * HDIM;
    float s = 0.f;
    for (int k = tid; k < HDIM; k += 128) s += pr[k] * wr[k];
    red[tid] = s;
    __syncthreads();
    for (int off = 64; off > 0; off >>= 1) {
        if (tid < off) red[tid] += red[tid + off];
        __syncthreads();
    }
    if (tid == 0) out[b * 2 + c] = red[0] + bp[c];
}

extern "C" void kernel_launch(void* const* d_in, const int* in_sizes, int n_in,
                              void* d_out, int out_size) {
    const int*   x     = (const int*)  d_in[0];
    const float* emb   = (const float*)d_in[1];
    const float* unk   = (const float*)d_in[2];
    const float* induc = (const float*)d_in[3];
    const float* W_ih  = (const float*)d_in[4];
    const float* W_hh  = (const float*)d_in[5];
    const float* b_ih  = (const float*)d_in[6];
    const float* b_hh  = (const float*)d_in[7];
    const float* W_pr  = (const float*)d_in[8];
    const float* b_pr  = (const float*)d_in[9];
    float* out = (float*)d_out;

    size_t gru_smem = (32 * 516 + 12 * 512 + 16 * 3 * 32) * sizeof(float); // 96768 B
    cudaFuncSetAttribute(gru_kernel, cudaFuncAttributeMaxDynamicSharedMemorySize,
                         (int)gru_smem);

    init_kernel<<<1, 256>>>(induc, unk);
    gather_kernel<<<(SEQ * BATCH * 64) / 256, 256>>>(x, emb);
    dim3 gg(SEQ, G3 / 128);
    xi_gemm_kernel<<<gg, 256>>>(W_ih, b_ih);
    gru_kernel<<<NCTA, GRUT, gru_smem>>>(W_hh, b_hh);
    proj_kernel<<<BATCH * 2, 128>>>(W_pr, b_pr, out);
}

// round 8
// speedup vs baseline: 1.1905x; 1.1905x over previous
#include <cuda_runtime.h>
#include <math.h>

#define EDIM   256
#define HDIM   512
#define BATCH  32
#define SEQ    512
#define G3     1536
#define NCTA   128
#define DPC    4
#define GRUT   512

// ---- scratch (device globals; no allocations allowed) ----
__device__ float d_induced[EDIM];
__device__ float d_e2[SEQ * BATCH * EDIM];            // [t][b][k]
__device__ float d_xi[(size_t)SEQ * G3 * BATCH];      // [t][g][b]
__device__ float d_h[2 * BATCH * HDIM];               // [buf][b][k]
__device__ float d_pooled[BATCH * HDIM];              // [b][d]
__device__ unsigned d_cnt;
__device__ unsigned d_gen;

// ---- init: induced = induction @ unk, h0 = 0, barrier reset ----
__global__ void init_kernel(const float* __restrict__ induction,
                            const float* __restrict__ unk) {
    int i = threadIdx.x;                               // 256 threads
    if (i == 0) { d_cnt = 0u; d_gen = 0u; }
    const float* row = induction + (size_t)i * EDIM;
    float s = 0.f;
    #pragma unroll 4
    for (int j = 0; j < EDIM; j++) s += row[j] * unk[j];
    d_induced[i] = s;
    for (int f = i; f < BATCH * HDIM; f += 256) d_h[f] = 0.f;
}

// ---- gather: e2[t][b][:] = emb_table[tok] or induced ----
__global__ void gather_kernel(const int* __restrict__ x,
                              const float* __restrict__ emb) {
    int gid = blockIdx.x * 256 + threadIdx.x;          // one float4 each
    int row = gid >> 6;                                // (t,b)
    int q   = gid & 63;
    int t = row >> 5, b = row & 31;
    int tok = x[b * SEQ + t];
    float4 v;
    if (tok < 0) v = ((const float4*)d_induced)[q];
    else         v = *((const float4*)(emb + (size_t)tok * EDIM) + q);
    ((float4*)d_e2)[gid] = v;
}

// ---- xi GEMM: xi[t][g][b] = sum_k e2[t][b][k]*W_ih[g][k] + b_ih[g] ----
__global__ void __launch_bounds__(256) xi_gemm_kernel(const float* __restrict__ W_ih,
                                                      const float* __restrict__ b_ih) {
    __shared__ __align__(16) float e_s[32 * 260];
    __shared__ __align__(16) float w_s[128 * 16];
    int t  = blockIdx.x;
    int g0 = blockIdx.y * 128;
    int tid = threadIdx.x;
    int w = tid >> 5, lane = tid & 31;

    const float* esrc = d_e2 + (size_t)t * BATCH * EDIM;
    for (int f = tid; f < 32 * 256; f += 256)
        e_s[(f >> 8) * 260 + (f & 255)] = esrc[f];

    float acc[16];
    #pragma unroll
    for (int g = 0; g < 16; g++) acc[g] = 0.f;

    for (int kc = 0; kc < 256; kc += 16) {
        __syncthreads();
        for (int f = tid; f < 2048; f += 256)
            w_s[f] = W_ih[(size_t)(g0 + (f >> 4)) * EDIM + kc + (f & 15)];
        __syncthreads();
        const float* hrow = e_s + lane * 260 + kc;
        #pragma unroll
        for (int k4 = 0; k4 < 16; k4 += 4) {
            float4 hv = *(const float4*)(hrow + k4);
            #pragma unroll
            for (int g = 0; g < 16; g++) {
                float4 wv = *(const float4*)(w_s + (w * 16 + g) * 16 + k4);
                acc[g] += hv.x * wv.x + hv.y * wv.y + hv.z * wv.z + hv.w * wv.w;
            }
        }
    }
    float* orow = d_xi + ((size_t)t * G3 + g0 + w * 16) * BATCH + lane;
    #pragma unroll
    for (int g = 0; g < 16; g++)
        orow[(size_t)g * BATCH] = acc[g] + b_ih[g0 + w * 16 + g];
}

// ---- GRU recurrence v2: warp = K-chunk, all 12 rows per warp ----
// CTA owns dims d0..d0+3 (12 W_hh rows, stationary in smem). warp w owns
// k in [32w, 32w+32). lane = batch. Finalize by warps 0..3 (dl = w).
__global__ void __launch_bounds__(GRUT, 1)
gru_kernel(const float* __restrict__ W_hh, const float* __restrict__ b_hh) {
    extern __shared__ float sm[];
    float* h_s = sm;                        // [32][516]  (66048 B)
    float* w_s = sm + 32 * 516;             // [12][512]  (24576 B)
    float* red = w_s + 12 * 512;            // [16][12][32] (24576 B)

    const int tid  = threadIdx.x;
    const int w    = tid >> 5, lane = tid & 31;

    // stage W_hh slice once: row r = gate*4 + dd
    for (int f = tid; f < 12 * 512; f += GRUT) {
        int r = f >> 9, k = f & 511;
        int gate = r >> 2, dd = r & 3;
        w_s[f] = W_hh[((size_t)gate * HDIM + blockIdx.x * DPC + dd) * HDIM + k];
    }
    float bh0 = 0.f, bh1 = 0.f, bh2 = 0.f;
    int d = 0;
    if (w < 4) {
        d = blockIdx.x * DPC + w;
        bh0 = b_hh[d]; bh1 = b_hh[HDIM + d]; bh2 = b_hh[2 * HDIM + d];
    }
    float maxacc = -INFINITY;
    __syncthreads();

    for (int t = 0; t < SEQ; t++) {
        // 0) prefetch xi[t] (finalize warps) — consumed ~3k cyc later
        float xr = 0.f, xz = 0.f, xn = 0.f;
        if (w < 4) {
            const float* xib = d_xi + (size_t)t * G3 * BATCH;
            xr = xib[(size_t)(0 * HDIM + d) * BATCH + lane];
            xz = xib[(size_t)(1 * HDIM + d) * BATCH + lane];
            xn = xib[(size_t)(2 * HDIM + d) * BATCH + lane];
        }

        // 1) stage h_prev -> smem (coalesced float4, padded stride 516)
        const float4* hsrc = (const float4*)(d_h + (t & 1) * BATCH * HDIM);
        #pragma unroll
        for (int i = 0, f = tid; i < 8; i++, f += GRUT) {
            float4 v = hsrc[f];
            *(float4*)(h_s + (f >> 7) * 516 + (f & 127) * 4) = v;
        }
        __syncthreads();

        // 2) all 12 rows x this warp's 32-K chunk; each h float4 feeds 48 FMA
        float acc[12];
        #pragma unroll
        for (int r = 0; r < 12; r++) acc[r] = 0.f;
        const float* hrow  = h_s + lane * 516 + 32 * w;
        const float* wbase = w_s + 32 * w;
        #pragma unroll
        for (int i = 0; i < 8; i++) {
            float4 hv = *(const float4*)(hrow + 4 * i);
            #pragma unroll
            for (int r = 0; r < 12; r++) {
                float4 wv = *(const float4*)(wbase + r * 512 + 4 * i);  // broadcast
                acc[r] += hv.x * wv.x + hv.y * wv.y + hv.z * wv.z + hv.w * wv.w;
            }
        }
        #pragma unroll
        for (int r = 0; r < 12; r++)
            red[(w * 12 + r) * 32 + lane] = acc[r];
        __syncthreads();

        // 3) finalize gates (warps 0..3; warp dl = w handles dim d, lane = batch)
        if (w < 4) {
            float sr = 0.f, sz = 0.f, sn = 0.f;
            #pragma unroll
            for (int kc = 0; kc < 16; kc++) {
                sr += red[(kc * 12 + 0 * 4 + w) * 32 + lane];
                sz += red[(kc * 12 + 1 * 4 + w) * 32 + lane];
                sn += red[(kc * 12 + 2 * 4 + w) * 32 + lane];
            }
            float rg = 1.f / (1.f + expf(-(xr + sr + bh0)));
            float zg = 1.f / (1.f + expf(-(xz + sz + bh1)));
            float ng = tanhf(xn + rg * (sn + bh2));      // torch: b_hh_n inside r*(.)
            float hp = h_s[lane * 516 + d];
            float hnew = (1.f - zg) * ng + zg * hp;
            maxacc = fmaxf(maxacc, hnew);
            d_h[((t + 1) & 1) * BATCH * HDIM + lane * HDIM + d] = hnew;
        }

        // 4) grid barrier (monotonic counter)
        __syncthreads();
        __threadfence();
        if (tid == 0) {
            unsigned target = (unsigned)(t + 1) * NCTA;
            unsigned a = atomicAdd(&d_cnt, 1u) + 1u;
            if (a == target) {
                atomicExch(&d_gen, (unsigned)(t + 1));
            } else {
                while (*((volatile unsigned*)&d_gen) < (unsigned)(t + 1)) { }
            }
            __threadfence();
        }
        __syncthreads();
    }
    if (w < 4) d_pooled[lane * HDIM + d] = maxacc;
}

// ---- projection: out[b][c] = pooled[b] . W_proj[c] + b_proj[c] ----
__global__ void proj_kernel(const float* __restrict__ Wp,
                            const float* __restrict__ bp,
                            float* __restrict__ out) {
    __shared__ float red[128];
    int b = blockIdx.x >> 1, c = blockIdx.x & 1;
    int tid = threadIdx.x;
    const float* pr = d_pooled + b * HDIM;
    const float* wr = Wp + c * HDIM;
    float s = 0.f;
    for (int k = tid; k < HDIM; k += 128) s += pr[k] * wr[k];
    red[tid] = s;
    __syncthreads();
    for (int off = 64; off > 0; off >>= 1) {
        if (tid < off) red[tid] += red[tid + off];
        __syncthreads();
    }
    if (tid == 0) out[b * 2 + c] = red[0] + bp[c];
}

extern "C" void kernel_launch(void* const* d_in, const int* in_sizes, int n_in,
                              void* d_out, int out_size) {
    const int*   x     = (const int*)  d_in[0];
    const float* emb   = (const float*)d_in[1];
    const float* unk   = (const float*)d_in[2];
    const float* induc = (const float*)d_in[3];
    const float* W_ih  = (const float*)d_in[4];
    const float* W_hh  = (const float*)d_in[5];
    const float* b_ih  = (const float*)d_in[6];
    const float* b_hh  = (const float*)d_in[7];
    const float* W_pr  = (const float*)d_in[8];
    const float* b_pr  = (const float*)d_in[9];
    float* out = (float*)d_out;

    size_t gru_smem = (32 * 516 + 12 * 512 + 16 * 12 * 32) * sizeof(float); // 115200 B
    cudaFuncSetAttribute(gru_kernel, cudaFuncAttributeMaxDynamicSharedMemorySize,
                         (int)gru_smem);

    init_kernel<<<1, 256>>>(induc, unk);
    gather_kernel<<<(SEQ * BATCH * 64) / 256, 256>>>(x, emb);
    dim3 gg(SEQ, G3 / 128);
    xi_gemm_kernel<<<gg, 256>>>(W_ih, b_ih);
    gru_kernel<<<NCTA, GRUT, gru_smem>>>(W_hh, b_hh);
    proj_kernel<<<BATCH * 2, 128>>>(W_pr, b_pr, out);
}

// round 11
// speedup vs baseline: 1.2691x; 1.0660x over previous
#include <cuda_runtime.h>
#include <math.h>

#define EDIM   256
#define HDIM   512
#define BATCH  32
#define SEQ    512
#define G3     1536
#define NCTA   128
#define DPC    4
#define GRUT   512

// ---- f32x2 packed helpers (sm_103a FFMA2; full fp32 precision) ----
__device__ __forceinline__ void fma2(unsigned long long& a,
                                     unsigned long long x, unsigned long long y) {
    asm("fma.rn.f32x2 %0, %1, %2, %0;" : "+l"(a) : "l"(x), "l"(y));
}
__device__ __forceinline__ unsigned long long pk(float lo, float hi) {
    unsigned long long r;
    asm("mov.b64 %0, {%1, %2};" : "=l"(r) : "f"(lo), "f"(hi));
    return r;
}
__device__ __forceinline__ float2 upk(unsigned long long v) {
    float2 r; asm("mov.b64 {%0, %1}, %2;" : "=f"(r.x), "=f"(r.y) : "l"(v));
    return r;
}

// ---- scratch (device globals; no allocations allowed) ----
__device__ float d_induced[EDIM];
__device__ float d_e2[SEQ * BATCH * EDIM];            // [t][b][k]
__device__ float d_xi[(size_t)SEQ * G3 * BATCH];      // [t][g][b]
__device__ float d_h2[2 * HDIM * BATCH];              // [buf][d][b]  (transposed!)
__device__ float d_pooled[BATCH * HDIM];              // [b][d]
__device__ unsigned d_cnt;
__device__ unsigned d_gen;

// ---- init: induced = induction @ unk, h0 = 0, barrier reset ----
__global__ void init_kernel(const float* __restrict__ induction,
                            const float* __restrict__ unk) {
    int i = threadIdx.x;                               // 256 threads
    if (i == 0) { d_cnt = 0u; d_gen = 0u; }
    const float* row = induction + (size_t)i * EDIM;
    float s = 0.f;
    #pragma unroll 4
    for (int j = 0; j < EDIM; j++) s += row[j] * unk[j];
    d_induced[i] = s;
    for (int f = i; f < HDIM * BATCH; f += 256) d_h2[f] = 0.f;
}

// ---- gather: e2[t][b][:] = emb_table[tok] or induced ----
__global__ void gather_kernel(const int* __restrict__ x,
                              const float* __restrict__ emb) {
    int gid = blockIdx.x * 256 + threadIdx.x;          // one float4 each
    int row = gid >> 6;
    int q   = gid & 63;
    int t = row >> 5, b = row & 31;
    int tok = x[b * SEQ + t];
    float4 v;
    if (tok < 0) v = ((const float4*)d_induced)[q];
    else         v = *((const float4*)(emb + (size_t)tok * EDIM) + q);
    ((float4*)d_e2)[gid] = v;
}

// ---- xi GEMM (f32x2): xi[t][g][b] = sum_k e2[t][b][k]*W_ih[g][k] + b_ih[g] ----
__global__ void __launch_bounds__(256) xi_gemm_kernel(const float* __restrict__ W_ih,
                                                      const float* __restrict__ b_ih) {
    __shared__ __align__(16) float e_s[32 * 260];
    __shared__ __align__(16) float w_s[128 * 16];
    int t  = blockIdx.x;
    int g0 = blockIdx.y * 128;
    int tid = threadIdx.x;
    int w = tid >> 5, lane = tid & 31;

    const float* esrc = d_e2 + (size_t)t * BATCH * EDIM;
    for (int f = tid; f < 32 * 256; f += 256)
        e_s[(f >> 8) * 260 + (f & 255)] = esrc[f];

    unsigned long long acc[16];
    #pragma unroll
    for (int g = 0; g < 16; g++) acc[g] = 0ull;

    for (int kc = 0; kc < 256; kc += 16) {
        __syncthreads();
        for (int f = tid; f < 2048; f += 256)
            w_s[f] = W_ih[(size_t)(g0 + (f >> 4)) * EDIM + kc + (f & 15)];
        __syncthreads();
        const float* hrow = e_s + lane * 260 + kc;
        #pragma unroll
        for (int k4 = 0; k4 < 16; k4 += 4) {
            ulonglong2 hv = *(const ulonglong2*)(hrow + k4);
            #pragma unroll
            for (int g = 0; g < 16; g++) {
                ulonglong2 wv = *(const ulonglong2*)(w_s + (w * 16 + g) * 16 + k4);
                fma2(acc[g], hv.x, wv.x);
                fma2(acc[g], hv.y, wv.y);
            }
        }
    }
    float* orow = d_xi + ((size_t)t * G3 + g0 + w * 16) * BATCH + lane;
    #pragma unroll
    for (int g = 0; g < 16; g++) {
        float2 p = upk(acc[g]);
        orow[(size_t)g * BATCH] = p.x + p.y + b_ih[g0 + w * 16 + g];
    }
}

// ---- GRU recurrence v3: f32x2 FMA, transposed h, no smem staging ----
// CTA owns dims d0..d0+3 (12 W_hh rows stationary in smem). warp w owns
// k in [32w,32w+32), lane = batch. h global layout [buf][k][b] -> coalesced
// LDG per k, coalesced STG per dim. Finalize by warps 0..3 (dim = w).
__global__ void __launch_bounds__(GRUT, 1)
gru_kernel(const float* __restrict__ W_hh, const float* __restrict__ b_hh) {
    extern __shared__ float sm[];
    float* w_s = sm;                        // [12][512]    (24576 B)
    float* red = sm + 12 * 512;             // [16][12][32] (24576 B)

    const int tid  = threadIdx.x;
    const int w    = tid >> 5, lane = tid & 31;

    for (int f = tid; f < 12 * 512; f += GRUT) {
        int r = f >> 9, k = f & 511;
        int gate = r >> 2, dd = r & 3;
        w_s[f] = W_hh[((size_t)gate * HDIM + blockIdx.x * DPC + dd) * HDIM + k];
    }
    float bh0 = 0.f, bh1 = 0.f, bh2 = 0.f;
    int d = 0;
    if (w < 4) {
        d = blockIdx.x * DPC + w;
        bh0 = b_hh[d]; bh1 = b_hh[HDIM + d]; bh2 = b_hh[2 * HDIM + d];
    }
    float maxacc = -INFINITY;
    __syncthreads();

    for (int t = 0; t < SEQ; t++) {
        const float* hbuf = d_h2 + (t & 1) * HDIM * BATCH;

        // 0) prefetch xi[t] + h_prev[d] (finalize warps)
        float xr = 0.f, xz = 0.f, xn = 0.f, hp = 0.f;
        if (w < 4) {
            const float* xib = d_xi + (size_t)t * G3 * BATCH;
            xr = xib[(size_t)(0 * HDIM + d) * BATCH + lane];
            xz = xib[(size_t)(1 * HDIM + d) * BATCH + lane];
            xn = xib[(size_t)(2 * HDIM + d) * BATCH + lane];
            hp = hbuf[d * BATCH + lane];
        }

        // 1) load this warp's h K-chunk directly (32 coalesced LDG, MLP=32)
        float hk[32];
        const float* hc = hbuf + 32 * w * BATCH + lane;
        #pragma unroll
        for (int i = 0; i < 32; i++) hk[i] = hc[i * BATCH];
        unsigned long long h2[16];
        #pragma unroll
        for (int i = 0; i < 16; i++) h2[i] = pk(hk[2 * i], hk[2 * i + 1]);

        // 2) all 12 rows x 32-K chunk via packed FFMA2 (192 instr/thread)
        unsigned long long acc[12];
        #pragma unroll
        for (int r = 0; r < 12; r++) acc[r] = 0ull;
        #pragma unroll
        for (int i = 0; i < 8; i++) {
            unsigned long long ha = h2[2 * i], hb = h2[2 * i + 1];
            #pragma unroll
            for (int r = 0; r < 12; r++) {
                ulonglong2 wv = *(const ulonglong2*)(w_s + r * 512 + 32 * w + 4 * i);
                fma2(acc[r], ha, wv.x);
                fma2(acc[r], hb, wv.y);
            }
        }
        #pragma unroll
        for (int r = 0; r < 12; r++) {
            float2 p = upk(acc[r]);
            red[(w * 12 + r) * 32 + lane] = p.x + p.y;
        }
        __syncthreads();

        // 3) finalize gates (warps 0..3; warp w = local dim, lane = batch)
        if (w < 4) {
            float sr = 0.f, sz = 0.f, sn = 0.f;
            #pragma unroll
            for (int kc = 0; kc < 16; kc++) {
                sr += red[(kc * 12 + 0 * 4 + w) * 32 + lane];
                sz += red[(kc * 12 + 1 * 4 + w) * 32 + lane];
                sn += red[(kc * 12 + 2 * 4 + w) * 32 + lane];
            }
            float rg = 1.f / (1.f + expf(-(xr + sr + bh0)));
            float zg = 1.f / (1.f + expf(-(xz + sz + bh1)));
            float ng = tanhf(xn + rg * (sn + bh2));      // torch: b_hh_n inside r*(.)
            float hnew = (1.f - zg) * ng + zg * hp;
            maxacc = fmaxf(maxacc, hnew);
            d_h2[((t + 1) & 1) * HDIM * BATCH + d * BATCH + lane] = hnew;  // coalesced
        }

        // 4) grid barrier (monotonic counter)
        __syncthreads();
        __threadfence();
        if (tid == 0) {
            unsigned target = (unsigned)(t + 1) * NCTA;
            unsigned a = atomicAdd(&d_cnt, 1u) + 1u;
            if (a == target) {
                atomicExch(&d_gen, (unsigned)(t + 1));
            } else {
                while (*((volatile unsigned*)&d_gen) < (unsigned)(t + 1)) { }
            }
            __threadfence();
        }
        __syncthreads();
    }
    if (w < 4) d_pooled[lane * HDIM + d] = maxacc;
}

// ---- projection: out[b][c] = pooled[b] . W_proj[c] + b_proj[c] ----
__global__ void proj_kernel(const float* __restrict__ Wp,
                            const float* __restrict__ bp,
                            float* __restrict__ out) {
    __shared__ float red[128];
    int b = blockIdx.x >> 1, c = blockIdx.x & 1;
    int tid = threadIdx.x;
    const float* pr = d_pooled + b * HDIM;
    const float* wr = Wp + c * HDIM;
    float s = 0.f;
    for (int k = tid; k < HDIM; k += 128) s += pr[k] * wr[k];
    red[tid] = s;
    __syncthreads();
    for (int off = 64; off > 0; off >>= 1) {
        if (tid < off) red[tid] += red[tid + off];
        __syncthreads();
    }
    if (tid == 0) out[b * 2 + c] = red[0] + bp[c];
}

extern "C" void kernel_launch(void* const* d_in, const int* in_sizes, int n_in,
                              void* d_out, int out_size) {
    const int*   x     = (const int*)  d_in[0];
    const float* emb   = (const float*)d_in[1];
    const float* unk   = (const float*)d_in[2];
    const float* induc = (const float*)d_in[3];
    const float* W_ih  = (const float*)d_in[4];
    const float* W_hh  = (const float*)d_in[5];
    const float* b_ih  = (const float*)d_in[6];
    const float* b_hh  = (const float*)d_in[7];
    const float* W_pr  = (const float*)d_in[8];
    const float* b_pr  = (const float*)d_in[9];
    float* out = (float*)d_out;

    size_t gru_smem = (12 * 512 + 16 * 12 * 32) * sizeof(float);  // 49152 B
    cudaFuncSetAttribute(gru_kernel, cudaFuncAttributeMaxDynamicSharedMemorySize,
                         (int)gru_smem);

    init_kernel<<<1, 256>>>(induc, unk);
    gather_kernel<<<(SEQ * BATCH * 64) / 256, 256>>>(x, emb);
    dim3 gg(SEQ, G3 / 128);
    xi_gemm_kernel<<<gg, 256>>>(W_ih, b_ih);
    gru_kernel<<<NCTA, GRUT, gru_smem>>>(W_hh, b_hh);
    proj_kernel<<<BATCH * 2, 128>>>(W_pr, b_pr, out);
}

// round 14
// speedup vs baseline: 1.5110x; 1.1906x over previous
#include <cuda_runtime.h>
#include <math.h>

#define EDIM   256
#define HDIM   512
#define BATCH  32
#define SEQ    512
#define G3     1536
#define NCTA   128
#define DPC    4
#define GRUT   512

// ---- f32x2 packed helpers (sm_103a FFMA2; full fp32 precision) ----
__device__ __forceinline__ void fma2(unsigned long long& a,
                                     unsigned long long x, unsigned long long y) {
    asm("fma.rn.f32x2 %0, %1, %2, %0;" : "+l"(a) : "l"(x), "l"(y));
}
__device__ __forceinline__ unsigned long long pk(float lo, float hi) {
    unsigned long long r;
    asm("mov.b64 %0, {%1, %2};" : "=l"(r) : "f"(lo), "f"(hi));
    return r;
}
__device__ __forceinline__ float2 upk(unsigned long long v) {
    float2 r; asm("mov.b64 {%0, %1}, %2;" : "=f"(r.x), "=f"(r.y) : "l"(v));
    return r;
}
__device__ __forceinline__ float ldcg(const float* p) {
    float v; asm volatile("ld.global.cg.f32 %0, [%1];" : "=f"(v) : "l"(p));
    return v;
}
__device__ __forceinline__ void stcg(float* p, float v) {
    asm volatile("st.global.cg.f32 [%0], %1;" :: "l"(p), "f"(v));
}

// ---- scratch (device globals; no allocations allowed) ----
__device__ float d_induced[EDIM];
__device__ float d_e2[SEQ * BATCH * EDIM];            // [t][b][k]
__device__ float d_xi[(size_t)SEQ * G3 * BATCH];      // [t][g][b]
__device__ float d_h2[2 * HDIM * BATCH];              // [buf][d][b]
__device__ float d_pooled[BATCH * HDIM];              // [b][d]
__device__ unsigned d_cnt;                            // monotonic arrival counter
__device__ unsigned d_gen;                            // released generation

// ---- init: induced = induction @ unk, h0 = 0, barrier reset ----
__global__ void init_kernel(const float* __restrict__ induction,
                            const float* __restrict__ unk) {
    int i = threadIdx.x;                               // 256 threads
    if (i == 0) { d_cnt = 0u; d_gen = 0u; }
    const float* row = induction + (size_t)i * EDIM;
    float s = 0.f;
    #pragma unroll 4
    for (int j = 0; j < EDIM; j++) s += row[j] * unk[j];
    d_induced[i] = s;
    for (int f = i; f < HDIM * BATCH; f += 256) d_h2[f] = 0.f;
}

// ---- gather: e2[t][b][:] = emb_table[tok] or induced ----
__global__ void gather_kernel(const int* __restrict__ x,
                              const float* __restrict__ emb) {
    int gid = blockIdx.x * 256 + threadIdx.x;          // one float4 each
    int row = gid >> 6;
    int q   = gid & 63;
    int t = row >> 5, b = row & 31;
    int tok = x[b * SEQ + t];
    float4 v;
    if (tok < 0) v = ((const float4*)d_induced)[q];
    else         v = *((const float4*)(emb + (size_t)tok * EDIM) + q);
    ((float4*)d_e2)[gid] = v;
}

// ---- xi GEMM (f32x2): xi[t][g][b] = sum_k e2[t][b][k]*W_ih[g][k] + b_ih[g] ----
__global__ void __launch_bounds__(256) xi_gemm_kernel(const float* __restrict__ W_ih,
                                                      const float* __restrict__ b_ih) {
    __shared__ __align__(16) float e_s[32 * 260];
    __shared__ __align__(16) float w_s[128 * 16];
    int t  = blockIdx.x;
    int g0 = blockIdx.y * 128;
    int tid = threadIdx.x;
    int w = tid >> 5, lane = tid & 31;

    const float* esrc = d_e2 + (size_t)t * BATCH * EDIM;
    for (int f = tid; f < 32 * 256; f += 256)
        e_s[(f >> 8) * 260 + (f & 255)] = esrc[f];

    unsigned long long acc[16];
    #pragma unroll
    for (int g = 0; g < 16; g++) acc[g] = 0ull;

    for (int kc = 0; kc < 256; kc += 16) {
        __syncthreads();
        for (int f = tid; f < 2048; f += 256)
            w_s[f] = W_ih[(size_t)(g0 + (f >> 4)) * EDIM + kc + (f & 15)];
        __syncthreads();
        const float* hrow = e_s + lane * 260 + kc;
        #pragma unroll
        for (int k4 = 0; k4 < 16; k4 += 4) {
            ulonglong2 hv = *(const ulonglong2*)(hrow + k4);
            #pragma unroll
            for (int g = 0; g < 16; g++) {
                ulonglong2 wv = *(const ulonglong2*)(w_s + (w * 16 + g) * 16 + k4);
                fma2(acc[g], hv.x, wv.x);
                fma2(acc[g], hv.y, wv.y);
            }
        }
    }
    float* orow = d_xi + ((size_t)t * G3 + g0 + w * 16) * BATCH + lane;
    #pragma unroll
    for (int g = 0; g < 16; g++) {
        float2 p = upk(acc[g]);
        orow[(size_t)g * BATCH] = p.x + p.y + b_ih[g0 + w * 16 + g];
    }
}

// ---- GRU recurrence v6: proven atomic barrier, trimmed overheads ----
// CTA owns dims d0..d0+3 (12 W_hh rows in smem). warp w owns k in [32w,32w+32).
// lane = batch. h layout [buf][d][b]; h traffic via .cg (L2-coherent, no L1
// staleness). Writers fence, tid0 does atomicAdd arrival + volatile poll on
// d_gen release (threadFenceReduction idiom; passed at 3708 and 2922 us).
__global__ void __launch_bounds__(GRUT, 1)
gru_kernel(const float* __restrict__ W_hh, const float* __restrict__ b_hh) {
    extern __shared__ float sm[];
    float* w_s = sm;                        // [12][512]    (24576 B)
    float* red = sm + 12 * 512;             // [16][12][32] (24576 B)

    const int tid  = threadIdx.x;
    const int w    = tid >> 5, lane = tid & 31;

    for (int f = tid; f < 12 * 512; f += GRUT) {
        int r = f >> 9, k = f & 511;
        int gate = r >> 2, dd = r & 3;
        w_s[f] = W_hh[((size_t)gate * HDIM + blockIdx.x * DPC + dd) * HDIM + k];
    }
    float bh0 = 0.f, bh1 = 0.f, bh2 = 0.f;
    int d = 0;
    if (w < 4) {
        d = blockIdx.x * DPC + w;
        bh0 = b_hh[d]; bh1 = b_hh[HDIM + d]; bh2 = b_hh[2 * HDIM + d];
    }
    float maxacc = -INFINITY;
    float hp = 0.f;                         // own h[d][lane], register-carried
    __syncthreads();

    for (int t = 0; t < SEQ; t++) {
        const float* hbuf = d_h2 + (t & 1) * HDIM * BATCH;

        // 0) prefetch xi[t] (finalize warps) — long-latency, hidden by dot
        float xr = 0.f, xz = 0.f, xn = 0.f;
        if (w < 4) {
            const float* xib = d_xi + (size_t)t * G3 * BATCH;
            xr = xib[(size_t)(0 * HDIM + d) * BATCH + lane];
            xz = xib[(size_t)(1 * HDIM + d) * BATCH + lane];
            xn = xib[(size_t)(2 * HDIM + d) * BATCH + lane];
        }

        // 1) load h chunk (32 coalesced .cg loads, MLP=32)
        float hk[32];
        const float* hc = hbuf + 32 * w * BATCH + lane;
        #pragma unroll
        for (int i = 0; i < 32; i++) hk[i] = ldcg(hc + i * BATCH);
        unsigned long long h2[16];
        #pragma unroll
        for (int i = 0; i < 16; i++) h2[i] = pk(hk[2 * i], hk[2 * i + 1]);

        // 2) all 12 rows x 32-K chunk via packed FFMA2 (192 instr/thread)
        unsigned long long acc[12];
        #pragma unroll
        for (int r = 0; r < 12; r++) acc[r] = 0ull;
        #pragma unroll
        for (int i = 0; i < 8; i++) {
            unsigned long long ha = h2[2 * i], hb = h2[2 * i + 1];
            #pragma unroll
            for (int r = 0; r < 12; r++) {
                ulonglong2 wv = *(const ulonglong2*)(w_s + r * 512 + 32 * w + 4 * i);
                fma2(acc[r], ha, wv.x);
                fma2(acc[r], hb, wv.y);
            }
        }
        #pragma unroll
        for (int r = 0; r < 12; r++) {
            float2 p = upk(acc[r]);
            red[(w * 12 + r) * 32 + lane] = p.x + p.y;
        }
        __syncthreads();

        // 3) finalize gates (warps 0..3; warp w = local dim, lane = batch)
        if (w < 4) {
            float sr = 0.f, sz = 0.f, sn = 0.f;
            #pragma unroll
            for (int kc = 0; kc < 16; kc++) {
                sr += red[(kc * 12 + 0 * 4 + w) * 32 + lane];
                sz += red[(kc * 12 + 1 * 4 + w) * 32 + lane];
                sn += red[(kc * 12 + 2 * 4 + w) * 32 + lane];
            }
            float rg = 1.f / (1.f + expf(-(xr + sr + bh0)));
            float zg = 1.f / (1.f + expf(-(xz + sz + bh1)));
            float ng = tanhf(xn + rg * (sn + bh2));      // torch: b_hh_n inside r*(.)
            float hnew = (1.f - zg) * ng + zg * hp;
            maxacc = fmaxf(maxacc, hnew);
            hp = hnew;
            stcg(d_h2 + ((t + 1) & 1) * HDIM * BATCH + d * BATCH + lane, hnew);
            __threadfence();                 // writers only: h visible pre-arrival
        }
        __syncthreads();                     // all writers fenced CTA-wide

        // 4) grid barrier: proven atomicAdd arrival + d_gen release
        if (t < SEQ - 1) {
            if (tid == 0) {
                unsigned target = (unsigned)(t + 1) * NCTA;
                unsigned a = atomicAdd(&d_cnt, 1u) + 1u;
                if (a == target) {
                    atomicExch(&d_gen, (unsigned)(t + 1));
                } else {
                    while (*((volatile unsigned*)&d_gen) < (unsigned)(t + 1)) { }
                }
            }
            __syncthreads();                 // release whole CTA
        }
    }
    if (w < 4) d_pooled[lane * HDIM + d] = maxacc;
}

// ---- projection: out[b][c] = pooled[b] . W_proj[c] + b_proj[c] ----
__global__ void proj_kernel(const float* __restrict__ Wp,
                            const float* __restrict__ bp,
                            float* __restrict__ out) {
    __shared__ float red[128];
    int b = blockIdx.x >> 1, c = blockIdx.x & 1;
    int tid = threadIdx.x;
    const float* pr = d_pooled + b * HDIM;
    const float* wr = Wp + c * HDIM;
    float s = 0.f;
    for (int k = tid; k < HDIM; k += 128) s += pr[k] * wr[k];
    red[tid] = s;
    __syncthreads();
    for (int off = 64; off > 0; off >>= 1) {
        if (tid < off) red[tid] += red[tid + off];
        __syncthreads();
    }
    if (tid == 0) out[b * 2 + c] = red[0] + bp[c];
}

extern "C" void kernel_launch(void* const* d_in, const int* in_sizes, int n_in,
                              void* d_out, int out_size) {
    const int*   x     = (const int*)  d_in[0];
    const float* emb   = (const float*)d_in[1];
    const float* unk   = (const float*)d_in[2];
    const float* induc = (const float*)d_in[3];
    const float* W_ih  = (const float*)d_in[4];
    const float* W_hh  = (const float*)d_in[5];
    const float* b_ih  = (const float*)d_in[6];
    const float* b_hh  = (const float*)d_in[7];
    const float* W_pr  = (const float*)d_in[8];
    const float* b_pr  = (const float*)d_in[9];
    float* out = (float*)d_out;

    size_t gru_smem = (12 * 512 + 16 * 12 * 32) * sizeof(float);  // 49152 B
    cudaFuncSetAttribute(gru_kernel, cudaFuncAttributeMaxDynamicSharedMemorySize,
                         (int)gru_smem);

    init_kernel<<<1, 256>>>(induc, unk);
    gather_kernel<<<(SEQ * BATCH * 64) / 256, 256>>>(x, emb);
    dim3 gg(SEQ, G3 / 128);
    xi_gemm_kernel<<<gg, 256>>>(W_ih, b_ih);
    gru_kernel<<<NCTA, GRUT, gru_smem>>>(W_hh, b_hh);
    proj_kernel<<<BATCH * 2, 128>>>(W_pr, b_pr, out);
}